// round 17
// baseline (speedup 1.0000x reference)
#include <cuda_runtime.h>
#include <cstdint>

// NMS_5549097746496: fused 8x8x8 MaxPool -> MaxUnpool -> threshold(0.5) -> (thresholded == x)
// Input:  raw [2,3,128,256,256] fp32 ; Output: mask as float32 0/1.
//
// out[i] = (x[i]==0) ? 1 : 0 everywhere, EXCEPT the block-argmax position when
// bmax > 0.5, which is 1. Output is therefore ~all zeros (1 per 512 elements).
//
// R17: split-phase to kill the DRAM read/write turnaround tax (mixed stream
// measured 5.8TB/s = 71% across R13/R14/R16; pure-direction streams reach ~90%).
//   kernel 1: pure-write zero-fill of the 201MB output (contiguous STG.128).
//   kernel 2: pure-read sweep (burst-16 LDG.128, proven mapping/config) +
//             sparse writes only: predicated x==0 stores (never fire for
//             Gaussian data, kept for exactness) + 1 store per hot window.
// Stream order serializes fill -> compute; hot-argmax write (value > 0.5) and
// x==0 writes are provably disjoint addresses.
//
// Argmax via packed key: key64 = (orderable(f) << 32) | (511 - e), u64 max ==
// lexicographic (value desc, K-index asc) == reference first-occurrence argmax.

#define NMS_HOT_KEY 0xBF000000u   // orderable(0.5f)

__device__ __forceinline__ unsigned ordkey(float f) {
    unsigned b = __float_as_uint(f);
    unsigned m = (unsigned)((int)b >> 31);   // sign-spread
    return b ^ (m | 0x80000000u);            // monotone in f
}

// ---------------- kernel 1: pure-write zero fill ----------------
__global__ __launch_bounds__(256)
void nms_zero_kernel(float4* __restrict__ o, int n4) {
    int i      = blockIdx.x * blockDim.x + threadIdx.x;
    int stride = gridDim.x * blockDim.x;
    const float4 z = make_float4(0.0f, 0.0f, 0.0f, 0.0f);
    for (; i < n4; i += stride)
        __stcs(o + i, z);
}

// ---------------- kernel 2: pure-read sweep + sparse writes ----------------
__global__ __launch_bounds__(64, 12)
void nms_mask_kernel(const float* __restrict__ in, float* __restrict__ out) {
    const int W = 256;
    const int HW = 256 * 256;

    int bid  = blockIdx.x;        // 6 * 16 * 32 * 2 = 6144
    int wseg = bid & 1;           // 128-float half of the w row
    int hblk = (bid >> 1) & 31;   // 32 h-windows
    int dblk = (bid >> 6) & 15;   // 16 d-windows
    int bc   = bid >> 10;         // 6

    int lane = threadIdx.x & 31;
    int warp = threadIdx.x >> 5;  // 0..1, 64-float w-span within the segment
    int win  = lane >> 2;         // 0..7  window within warp span
    int dzh  = (lane >> 1) & 1;   // 0..1  dz half (dz = dzh*4 + dzl)
    int wc   = lane & 1;          // 0..1  16B chunk within window row

    // window-origin offset (dz=0,dy=0,dx=0) for this lane's window
    size_t wbase = ((size_t)(bc * 128 + dblk * 8)) * HW
                 + (size_t)(hblk * 8) * W
                 + (size_t)(wseg * 128 + warp * 64 + win * 8);
    // this lane's chunk base
    size_t mybase = wbase + (size_t)dzh * 4 * HW + (size_t)wc * 4;

    const float* p = in  + mybase;
    float*       q = out + mybase;

    unsigned long long bestK = 0ull;

    #pragma unroll
    for (int half = 0; half < 2; half++) {
        const int dz0 = half * 2;   // planes dz0, dz0+1 of this dz-half

        // ---- stage two dz-planes: 16 independent LDG.128 (MLP=16) ----
        float4 v[2][8];
        #pragma unroll
        for (int pl = 0; pl < 2; pl++)
            #pragma unroll
            for (int dy = 0; dy < 8; dy++)
                v[pl][dy] = __ldcs(reinterpret_cast<const float4*>(
                                p + (dz0 + pl) * HW + dy * W));

        // ---- packed-key argmax + rare x==0 writes (predicated, ~never fire) ----
        #pragma unroll
        for (int pl = 0; pl < 2; pl++) {
            #pragma unroll
            for (int dy = 0; dy < 8; dy++) {
                float4 x = v[pl][dy];
                float*  qp = q + (dz0 + pl) * HW + dy * W;

                // faithful x==0 quirk (catches +-0); predicated stores, no branch
                if (x.x == 0.0f) qp[0] = 1.0f;
                if (x.y == 0.0f) qp[1] = 1.0f;
                if (x.z == 0.0f) qp[2] = 1.0f;
                if (x.w == 0.0f) qp[3] = 1.0f;

                int eb = (dzh * 4 + dz0 + pl) * 64 + dy * 8 + wc * 4;  // K-index, 0..511
                unsigned long long k0 = ((unsigned long long)ordkey(x.x) << 32) | (unsigned)(511 - (eb + 0));
                unsigned long long k1 = ((unsigned long long)ordkey(x.y) << 32) | (unsigned)(511 - (eb + 1));
                unsigned long long k2 = ((unsigned long long)ordkey(x.z) << 32) | (unsigned)(511 - (eb + 2));
                unsigned long long k3 = ((unsigned long long)ordkey(x.w) << 32) | (unsigned)(511 - (eb + 3));
                unsigned long long ka = k0 > k1 ? k0 : k1;
                unsigned long long kb = k2 > k3 ? k2 : k3;
                unsigned long long kc = ka > kb ? ka : kb;
                bestK = kc > bestK ? kc : bestK;
            }
        }
    }

    // remember local candidate to identify the owning lane afterwards
    unsigned long long lK = bestK;

    // reduce across the 4 lanes of this window (xor 1,2 stays in aligned group of 4)
    #pragma unroll
    for (int msk = 1; msk < 4; msk <<= 1) {
        unsigned long long ok = __shfl_xor_sync(0xffffffffu, bestK, msk);
        bestK = ok > bestK ? ok : bestK;
    }

    // the lane that loaded the winning element writes 1.0 at the argmax if hot.
    // key64 is unique across the window (e unique), so exactly one lane matches.
    unsigned bestKey32 = (unsigned)(bestK >> 32);
    if (bestKey32 > NMS_HOT_KEY && lK == bestK) {
        int e  = 511 - (int)(bestK & 511u);
        int dz = e >> 6, dy = (e >> 3) & 7, dx = e & 7;
        out[wbase + (size_t)dz * HW + (size_t)dy * W + dx] = 1.0f;
    }
}

extern "C" void kernel_launch(void* const* d_in, const int* in_sizes, int n_in,
                              void* d_out, int out_size) {
    (void)in_sizes; (void)n_in;
    const float* in = (const float*)d_in[0];
    float* out = (float*)d_out;

    // phase 1: pure-write zero fill (out_size = 100663296 floats -> 25165824 float4)
    int n4 = out_size >> 2;
    nms_zero_kernel<<<8192, 256>>>((float4*)out, n4);

    // phase 2: pure-read sweep + sparse writes (stream order serializes phases)
    nms_mask_kernel<<<6144, 64>>>(in, out);
}